// round 8
// baseline (speedup 1.0000x reference)
#include <cuda_runtime.h>
#include <cuda_bf16.h>

// ---------------------------------------------------------------------------
// QuantumLayerVQC as a trilinear form:
//   out[b] = sum_{a,b,c} T[a][b][c] * g0[a]*g1[b]*g2[c],  g_q = (1, cos x_q, sin x_q)
// T derived once per block from the fixed variational unitary U (w[3,3,2]) via
// M_ij = sum_k s_k (ReU_ki ReU_kj + ImU_ki ImU_kj) and per-qubit half-angle
// basis change: c^2=(1+cos)/2, cs=sin/2, s^2=(1-cos)/2.
// Qubit q <-> bitmask (4 >> q).
// ---------------------------------------------------------------------------

__device__ __forceinline__ float2 cmulf(float2 a, float2 b) {
    return make_float2(a.x * b.x - a.y * b.y, a.x * b.y + a.y * b.x);
}

template <int M>
__device__ __forceinline__ void ry_g(float2 st[8], float theta) {
    float s, c;
    __sincosf(0.5f * theta, &s, &c);
#pragma unroll
    for (int k = 0; k < 8; k++) {
        if (!(k & M)) {
            float2 a = st[k], b = st[k | M];
            st[k]     = make_float2(c * a.x - s * b.x, c * a.y - s * b.y);
            st[k | M] = make_float2(s * a.x + c * b.x, s * a.y + c * b.y);
        }
    }
}

template <int M>
__device__ __forceinline__ void rz_g(float2 st[8], float phi) {
    float s, c;
    __sincosf(0.5f * phi, &s, &c);
    float2 p0 = make_float2(c, -s);
    float2 p1 = make_float2(c,  s);
#pragma unroll
    for (int k = 0; k < 8; k++) st[k] = cmulf(st[k], (k & M) ? p1 : p0);
}

template <int CM, int TM>
__device__ __forceinline__ void cnot_g(float2 st[8]) {
#pragma unroll
    for (int k = 0; k < 8; k++) {
        if ((k & CM) && !(k & TM)) {
            float2 t = st[k];
            st[k] = st[k | TM];
            st[k | TM] = t;
        }
    }
}

// Nested Horner over register-resident T: 26 FMA + 6 MUFU, zero LDS.
__device__ __forceinline__ float trilinear_r(const float t[27], float4 r) {
    float c0, s0, c1, s1, c2, s2;
    __sincosf(r.x, &s0, &c0);
    __sincosf(r.y, &s1, &c1);
    __sincosf(r.z, &s2, &c2);

    float m[3];
#pragma unroll
    for (int a = 0; a < 3; a++) {
        const float i0 = fmaf(s2, t[a*9+2], fmaf(c2, t[a*9+1], t[a*9+0]));
        const float i1 = fmaf(s2, t[a*9+5], fmaf(c2, t[a*9+4], t[a*9+3]));
        const float i2 = fmaf(s2, t[a*9+8], fmaf(c2, t[a*9+7], t[a*9+6]));
        m[a] = fmaf(s1, i2, fmaf(c1, i1, i0));
    }
    return fmaf(s0, m[2], fmaf(c0, m[1], m[0]));
}

__global__ __launch_bounds__(256, 3) void vqc_kernel(
    const float* __restrict__ x,   // [n, 8]
    const float* __restrict__ w,   // [3, 3, 2]
    float* __restrict__ out,       // [n]
    int n)
{
    __shared__ float2 sU[8][8];
    __shared__ float  sM[64];
    __shared__ float  sP[216];     // phase-2b partials
    __shared__ float  sT[27];

    const int tid = threadIdx.x;

    // --- Phase 1: threads 0..7 simulate one basis column of U each ----------
    if (tid < 8) {
        float2 st[8];
#pragma unroll
        for (int k = 0; k < 8; k++) st[k] = make_float2(0.f, 0.f);
        st[tid] = make_float2(1.f, 0.f);

#pragma unroll
        for (int l = 0; l < 3; l++) {
            const float* wl = w + l * 6;
            ry_g<4>(st, wl[0]); rz_g<4>(st, wl[1]);
            ry_g<2>(st, wl[2]); rz_g<2>(st, wl[3]);
            ry_g<1>(st, wl[4]); rz_g<1>(st, wl[5]);
            cnot_g<4, 2>(st);
            cnot_g<2, 1>(st);
        }
#pragma unroll
        for (int k = 0; k < 8; k++) sU[k][tid] = st[k];
    }
    __syncthreads();

    // --- Phase 2: threads 0..63 build M --------------------------------------
    if (tid < 64) {
        const int i = tid >> 3, j = tid & 7;
        float m = 0.f;
#pragma unroll
        for (int k = 0; k < 8; k++) {
            float t = sU[k][i].x * sU[k][j].x + sU[k][i].y * sU[k][j].y;
            m += (k & 4) ? -t : t;
        }
        sM[tid] = m;
    }
    __syncthreads();

    // --- Phase 2b: 216 threads build T partials (i fixed per thread) ---------
    // Basis rows: W[0]={.5,.5,0}  W[1]=W[2]={0,0,.5}  W[3]={.5,-.5,0}
    if (tid < 216) {
        const int i  = tid / 27;
        const int m3 = tid % 27;
        const int a = m3 / 9, b = (m3 / 3) % 3, c = m3 % 3;

        // per-dim selected weights: p = i_bit*2 + j_bit
        const float w0a = (a < 2) ? 0.5f : 0.f;
        const float w12a = (a == 2) ? 0.5f : 0.f;
        const float w3a = (a == 0) ? 0.5f : ((a == 1) ? -0.5f : 0.f);
        const float w0b = (b < 2) ? 0.5f : 0.f;
        const float w12b = (b == 2) ? 0.5f : 0.f;
        const float w3b = (b == 0) ? 0.5f : ((b == 1) ? -0.5f : 0.f);
        const float w0c = (c < 2) ? 0.5f : 0.f;
        const float w12c = (c == 2) ? 0.5f : 0.f;
        const float w3c = (c == 0) ? 0.5f : ((c == 1) ? -0.5f : 0.f);

        const int ib0 = (i >> 2) & 1, ib1 = (i >> 1) & 1, ib2 = i & 1;
        const float a_lo = ib0 ? w12a : w0a,  a_hi = ib0 ? w3a : w12a;
        const float b_lo = ib1 ? w12b : w0b,  b_hi = ib1 ? w3b : w12b;
        const float c_lo = ib2 ? w12c : w0c,  c_hi = ib2 ? w3c : w12c;

        float acc = 0.f;
#pragma unroll
        for (int j = 0; j < 8; j++) {
            const float va = (j & 4) ? a_hi : a_lo;
            const float vb = (j & 2) ? b_hi : b_lo;
            const float vc = (j & 1) ? c_hi : c_lo;
            acc = fmaf(sM[i * 8 + j], va * vb * vc, acc);
        }
        sP[tid] = acc;
    }
    __syncthreads();

    if (tid < 27) {
        float acc = 0.f;
#pragma unroll
        for (int k = 0; k < 8; k++) acc += sP[k * 27 + tid];
        sT[tid] = acc;
    }
    __syncthreads();

    // --- Hoist T into registers (27 LDS total per thread) --------------------
    float t[27];
#pragma unroll
    for (int k = 0; k < 27; k++) t[k] = sT[k];

    // --- Phase 3: front-batched unroll-4 streaming (MLP_p1 = 4) --------------
    const int stride  = gridDim.x * blockDim.x;
    const int stride4 = stride * 4;

    for (int idx = blockIdx.x * blockDim.x + tid; idx < n; idx += stride4) {
        const int j1 = idx + stride, j2 = idx + 2 * stride, j3 = idx + 3 * stride;

        float4 r0 = __ldg(reinterpret_cast<const float4*>(x + (size_t)idx * 8));
        float4 r1, r2, r3;
        if (j1 < n) r1 = __ldg(reinterpret_cast<const float4*>(x + (size_t)j1 * 8));
        if (j2 < n) r2 = __ldg(reinterpret_cast<const float4*>(x + (size_t)j2 * 8));
        if (j3 < n) r3 = __ldg(reinterpret_cast<const float4*>(x + (size_t)j3 * 8));

        out[idx] = trilinear_r(t, r0);
        if (j1 < n) out[j1] = trilinear_r(t, r1);
        if (j2 < n) out[j2] = trilinear_r(t, r2);
        if (j3 < n) out[j3] = trilinear_r(t, r3);
    }
}

extern "C" void kernel_launch(void* const* d_in, const int* in_sizes, int n_in,
                              void* d_out, int out_size)
{
    const float* x = (const float*)d_in[0];   // [B, 8] f32
    const float* w = (const float*)d_in[1];   // [3, 3, 2] f32
    float* out = (float*)d_out;               // [B, 1] f32

    const int n = in_sizes[0] / 8;
    const int tpb = 256;
    const int blocks = 444;                   // 3 CTAs/SM * 148 SMs, unroll-4 + tail
    vqc_kernel<<<blocks, tpb>>>(x, w, out, n);
}